// round 4
// baseline (speedup 1.0000x reference)
#include <cuda_runtime.h>
#include <math.h>
#include <stdint.h>

#define B_ 32
#define S_ 512
#define E_ 300
#define F_ 100
#define T_ 50
#define EC 30   // e-chunk for emissions smem staging

// Scratch (no allocations allowed)
__device__ float  g_em[B_ * S_ * T_];      // emissions [B,S,T]
__device__ float  g_part[B_];
__device__ float2 g_wt2[E_ * 3 * F_];      // conv_w repacked+dup: [e][k][f] -> (w,w)
__device__ unsigned g_cnt;                 // last-block counter (self-resetting)

// ---- packed fp32x2 helpers (sm_103a) ----
#define PACK2(d, lo, hi) \
    asm("mov.b64 %0, {%1, %2};" : "=l"(d) : "r"(__float_as_uint(lo)), "r"(__float_as_uint(hi)))
#define FMA2(d, a, b) \
    asm("fma.rn.f32x2 %0, %1, %2, %0;" : "+l"(d) : "l"(a), "l"(b))
#define MUL2(d, a, b) \
    asm("mul.rn.f32x2 %0, %1, %2;" : "=l"(d) : "l"(a), "l"(b))
#define UNPACK2(lo, hi, v) do { unsigned _l, _h; \
    asm("mov.b64 {%0, %1}, %2;" : "=r"(_l), "=r"(_h) : "l"(v)); \
    lo = __uint_as_float(_l); hi = __uint_as_float(_h); } while (0)
// O = (hi(A), lo(B)) — register-pair merge (compiles to <=2 MOV)
#define MIDPAIR(o, a, b) \
    asm("{\n\t.reg .b32 al,ah,bl,bh;\n\tmov.b64 {al,ah}, %1;\n\tmov.b64 {bl,bh}, %2;\n\t" \
        "mov.b64 %0, {ah,bl};\n\t}" : "=l"(o) : "l"(a), "l"(b))

// ---------------------------------------------------------------------------
// Kernel 0: repack conv_w [F][E][K] -> g_wt2 [(e*3+k)][f] = float2(w,w)
// ---------------------------------------------------------------------------
__global__ void k_wt(const float* __restrict__ cw)
{
    int i = blockIdx.x * 256 + threadIdx.x;      // input order (coalesced reads)
    if (i < F_ * E_ * 3) {
        int f = i / (E_ * 3), r = i % (E_ * 3);  // r = e*3+k
        float w = cw[i];
        g_wt2[r * F_ + f] = make_float2(w, w);
    }
}

// ---------------------------------------------------------------------------
// Kernel 1: emb gather + conv1d(K=3,pad=1) + bias + ReLU + FC -> emissions
// Block: 256 threads, 64 s-positions of one batch row. grid = (8, 32).
// Compute threads (200): ft = tid>>3 (4 f each), sg = tid&7 (8 s = 4 s-pairs).
// Accumulators pack TWO ADJACENT s POSITIONS per f32x2: multiplicand pairs come
// straight from LDS (aligned for k=0,2; one register merge for k=1); weights are
// pre-duplicated in g_wt2 so LDG.128 gives broadcast-packed weights directly.
// ---------------------------------------------------------------------------
__global__ __launch_bounds__(256) void k_emissions(
    const int* __restrict__ x,
    const float* __restrict__ emb,
    const float* __restrict__ conv_b,
    const float* __restrict__ fc_w,     // [T,F]
    const float* __restrict__ fc_b)
{
    // phase1: sT[EC][68] (2040 fl) | phase2: feat[64][101] @0 (6464) + fcwT[100][52] @6464
    __shared__ __align__(16) float sbuf[11664];   // 46.7 KB
    __shared__ int sx[66];

    const int tid = threadIdx.x;
    const int b   = blockIdx.y;
    const int s0  = blockIdx.x * 64;

    float* sT   = sbuf;
    float* feat = sbuf;
    float* fcwT = sbuf + 6464;

    if (tid < 66) {
        int sg_ = s0 - 1 + tid;
        sx[tid] = (sg_ >= 0 && sg_ < S_) ? x[b * S_ + sg_] : -1;
    }
    // stage fc_w transposed [f][t], stride 52 (region disjoint from sT)
    for (int idx = tid; idx < T_ * F_; idx += 256) {
        int t = idx / F_, f = idx - t * F_;
        fcwT[f * 52 + t] = __ldg(&fc_w[idx]);
    }

    const int ft  = tid >> 3;        // f-group (valid < 25)
    const int sg  = tid & 7;         // s-group (8 s each)
    const bool act = (tid < 200);

    uint64_t acc[4][4];              // [s-pair][f]
    #pragma unroll
    for (int p = 0; p < 4; p++)
        #pragma unroll
        for (int j = 0; j < 4; j++) acc[p][j] = 0ull;

    for (int ec0 = 0; ec0 < E_; ec0 += EC) {
        __syncthreads();    // previous chunk's reads complete (covers init stages too)
        for (int idx = tid; idx < EC * 66; idx += 256) {
            int r = idx / EC, el = idx - r * EC;   // consecutive tid -> consecutive e
            int v = sx[r];
            sT[el * 68 + r] = (v >= 0) ? __ldg(&emb[v * E_ + ec0 + el]) : 0.f;
        }
        __syncthreads();
        if (act) {
            #pragma unroll 3
            for (int el = 0; el < EC; el++) {
                const float* row = sT + el * 68 + sg * 8;
                ulonglong2 q0 = *(const ulonglong2*)(row);       // A0=(s0,s1) A1=(s2,s3)
                ulonglong2 q1 = *(const ulonglong2*)(row + 4);   // A2,A3
                uint64_t   A4 = *(const uint64_t*)(row + 8);     // (s8,s9)
                uint64_t A[5] = {q0.x, q0.y, q1.x, q1.y, A4};
                uint64_t O[4];
                #pragma unroll
                for (int p = 0; p < 4; p++) MIDPAIR(O[p], A[p], A[p + 1]);

                const float2* wb = g_wt2 + (ec0 + el) * (3 * F_) + ft * 4;
                ulonglong2 w0a = __ldg((const ulonglong2*)(wb));            // k=0: f0,f1
                ulonglong2 w0b = __ldg((const ulonglong2*)(wb + 2));        //      f2,f3
                ulonglong2 w1a = __ldg((const ulonglong2*)(wb + F_));       // k=1
                ulonglong2 w1b = __ldg((const ulonglong2*)(wb + F_ + 2));
                ulonglong2 w2a = __ldg((const ulonglong2*)(wb + 2 * F_));   // k=2
                ulonglong2 w2b = __ldg((const ulonglong2*)(wb + 2 * F_ + 2));
                uint64_t W[3][4] = {
                    {w0a.x, w0a.y, w0b.x, w0b.y},
                    {w1a.x, w1a.y, w1b.x, w1b.y},
                    {w2a.x, w2a.y, w2b.x, w2b.y}};

                #pragma unroll
                for (int p = 0; p < 4; p++) {
                    #pragma unroll
                    for (int j = 0; j < 4; j++) {
                        FMA2(acc[p][j], A[p],     W[0][j]);
                        FMA2(acc[p][j], O[p],     W[1][j]);
                        FMA2(acc[p][j], A[p + 1], W[2][j]);
                    }
                }
            }
        }
    }
    __syncthreads();   // conv reads of sT done -> safe to overwrite with feat

    if (act) {
        #pragma unroll
        for (int j = 0; j < 4; j++) {
            float bb = __ldg(&conv_b[ft * 4 + j]);
            #pragma unroll
            for (int p = 0; p < 4; p++) {
                float h0, h1;
                UNPACK2(h0, h1, acc[p][j]);
                feat[(sg * 8 + 2 * p)     * 101 + ft * 4 + j] = fmaxf(h0 + bb, 0.f);
                feat[(sg * 8 + 2 * p + 1) * 101 + ft * 4 + j] = fmaxf(h1 + bb, 0.f);
            }
        }
    }
    __syncthreads();

    // FC: em[s][t] = feat[s][:] . fc_w[t][:] + fc_b[t]
    for (int idx = tid; idx < 64 * T_; idx += 256) {
        int s = idx / T_, t = idx - s * T_;
        float d = __ldg(&fc_b[t]);
        const float* fv = feat + s * 101;
        const float* fw = fcwT + t;
        #pragma unroll 10
        for (int f = 0; f < F_; f++) d += fv[f] * fw[f * 52];
        g_em[(b * S_ + (s0 + s)) * T_ + t] = d;
    }
}

// ---------------------------------------------------------------------------
// Kernel 2: CRF, single warp per batch, linear domain, shuffle-broadcast matvec.
// Thread t (<25) owns states j0=2t, j1=2t+1 (alpha packed f32x2).
// ---------------------------------------------------------------------------
__global__ __launch_bounds__(32) void k_crf(
    const int* __restrict__ tags,
    const float* __restrict__ start_trans,
    const float* __restrict__ end_trans,
    const float* __restrict__ trans,
    float* __restrict__ out)
{
    const int tid  = threadIdx.x;
    const int b    = blockIdx.x;
    const int base = b * S_;
    const bool act = (tid < 25);
    const int j0 = 2 * tid, j1 = 2 * tid + 1;

    uint64_t Ej0[25], Ej1[25];
    if (act) {
        #pragma unroll
        for (int i = 0; i < 25; i++) {
            float e00 = __expf(__ldg(&trans[(2 * i)     * T_ + j0]));
            float e01 = __expf(__ldg(&trans[(2 * i + 1) * T_ + j0]));
            float e10 = __expf(__ldg(&trans[(2 * i)     * T_ + j1]));
            float e11 = __expf(__ldg(&trans[(2 * i + 1) * T_ + j1]));
            PACK2(Ej0[i], e00, e01);
            PACK2(Ej1[i], e10, e11);
        }
    } else {
        #pragma unroll
        for (int i = 0; i < 25; i++) { Ej0[i] = 0ull; Ej1[i] = 0ull; }
    }

    // --- numerator: gold path score ---
    const int* tg = tags + base;
    float local = 0.f;
    for (int s = tid; s < S_; s += 32) {
        int t = __ldg(&tg[s]);
        local += __ldg(&g_em[(base + s) * T_ + t]);
        if (s < S_ - 1) local += __ldg(&trans[t * T_ + __ldg(&tg[s + 1])]);
    }
    #pragma unroll
    for (int o = 16; o; o >>= 1) local += __shfl_xor_sync(0xffffffffu, local, o);
    float s_num = local + __ldg(&start_trans[tg[0]]) + __ldg(&end_trans[tg[S_ - 1]]);

    // --- init alpha (log -> linear with offset) ---
    float al0 = -3.0e38f, al1 = -3.0e38f;
    if (act) {
        float2 e0 = *(const float2*)&g_em[base * T_ + j0];
        al0 = __ldg(&start_trans[j0]) + e0.x;
        al1 = __ldg(&start_trans[j1]) + e0.y;
    }
    float mv = fmaxf(al0, al1);
    #pragma unroll
    for (int o = 16; o; o >>= 1) mv = fmaxf(mv, __shfl_xor_sync(0xffffffffu, mv, o));
    float off = mv;
    uint64_t apk = 0ull;
    if (act) { PACK2(apk, __expf(al0 - mv), __expf(al1 - mv)); }

    // --- forward scan: 63 groups of 8 (s=1..504) + partial of 7 ---
    float2 bufA[8], bufB[8];
    #pragma unroll
    for (int k = 0; k < 8; k++) { bufA[k] = make_float2(0.f, 0.f); bufB[k] = make_float2(0.f, 0.f); }
    if (act) {
        #pragma unroll
        for (int k = 0; k < 8; k++)
            bufA[k] = __ldg((const float2*)&g_em[(base + 1 + k) * T_ + j0]);
    }

    for (int g = 0; g < 64; g++) {
        if (g < 63 && act) {
            int sn = 8 * g + 9;
            #pragma unroll
            for (int k = 0; k < 8; k++)
                if (sn + k < S_) bufB[k] = __ldg((const float2*)&g_em[(base + sn + k) * T_ + j0]);
        }
        uint64_t eem[8];
        #pragma unroll
        for (int k = 0; k < 8; k++) {
            float e0 = __expf(bufA[k].x), e1 = __expf(bufA[k].y);
            PACK2(eem[k], e0, e1);
        }
        const int nst = (g < 63) ? 8 : 7;
        #pragma unroll
        for (int k = 0; k < 8; k++) {
            if (k >= nst) break;
            uint64_t d00 = 0ull, d01 = 0ull, d10 = 0ull, d11 = 0ull;
            #pragma unroll
            for (int i = 0; i < 25; i++) {
                uint64_t pv = __shfl_sync(0xffffffffu, apk, i);
                if (i & 1) { FMA2(d01, pv, Ej0[i]); FMA2(d11, pv, Ej1[i]); }
                else       { FMA2(d00, pv, Ej0[i]); FMA2(d10, pv, Ej1[i]); }
            }
            float l, h;
            UNPACK2(l, h, d00); float sm0 = l + h;
            UNPACK2(l, h, d01); sm0 += l + h;
            UNPACK2(l, h, d10); float sm1 = l + h;
            UNPACK2(l, h, d11); sm1 += l + h;
            uint64_t sp;
            PACK2(sp, sm0, sm1);
            MUL2(apk, sp, eem[k]);   // inactive lanes: Ej=0 -> apk stays 0
        }
        if (g < 63) {
            float a0, a1;
            UNPACK2(a0, a1, apk);
            float m = fmaxf(a0, a1);
            #pragma unroll
            for (int o = 16; o; o >>= 1) m = fmaxf(m, __shfl_xor_sync(0xffffffffu, m, o));
            float inv = 1.0f / m;
            off += __logf(m);
            uint64_t ip; PACK2(ip, inv, inv);
            MUL2(apk, apk, ip);
        }
        #pragma unroll
        for (int k = 0; k < 8; k++) bufA[k] = bufB[k];
    }

    // --- log_z ---
    float av = 0.f;
    if (act) {
        float a0, a1; UNPACK2(a0, a1, apk);
        av = a0 * __expf(__ldg(&end_trans[j0])) + a1 * __expf(__ldg(&end_trans[j1]));
    }
    #pragma unroll
    for (int o = 16; o; o >>= 1) av += __shfl_xor_sync(0xffffffffu, av, o);
    if (tid == 0) g_part[b] = (off + logf(av)) - s_num;

    // --- last block reduces g_part -> out, resets counter ---
    unsigned isl = 0;
    if (tid == 0) {
        __threadfence();
        unsigned prev = atomicAdd(&g_cnt, 1u);
        isl = (prev == B_ - 1) ? 1u : 0u;
    }
    isl = __shfl_sync(0xffffffffu, isl, 0);
    if (isl) {
        __threadfence();
        float v = g_part[tid];
        #pragma unroll
        for (int o = 16; o; o >>= 1) v += __shfl_xor_sync(0xffffffffu, v, o);
        if (tid == 0) { out[0] = v; g_cnt = 0u; }
    }
}

// No-op: shifts ncu's "-s 5 -c 1" window onto iteration-2's k_emissions.
__global__ void k_nop() {}

extern "C" void kernel_launch(void* const* d_in, const int* in_sizes, int n_in,
                              void* d_out, int out_size)
{
    const int*   x           = (const int*)  d_in[0];
    const int*   tags        = (const int*)  d_in[1];
    const float* emb         = (const float*)d_in[2];
    const float* conv_w      = (const float*)d_in[3];
    const float* conv_b      = (const float*)d_in[4];
    const float* fc_w        = (const float*)d_in[5];
    const float* fc_b        = (const float*)d_in[6];
    const float* start_trans = (const float*)d_in[7];
    const float* end_trans   = (const float*)d_in[8];
    const float* trans       = (const float*)d_in[9];
    float* out = (float*)d_out;

    k_wt<<<(F_ * E_ * 3 + 255) / 256, 256>>>(conv_w);
    k_emissions<<<dim3(S_ / 64, B_), 256>>>(x, emb, conv_b, fc_w, fc_b);
    k_crf<<<B_, 32>>>(tags, start_trans, end_trans, trans, out);
    k_nop<<<1, 1>>>();
}

// round 5
// speedup vs baseline: 1.5681x; 1.5681x over previous
#include <cuda_runtime.h>
#include <math.h>
#include <stdint.h>

#define B_ 32
#define S_ 512
#define E_ 300
#define F_ 100
#define T_ 50

// Scratch (no allocations allowed)
__device__ float g_em[B_ * S_ * T_];                   // emissions [B,S,T]
__device__ float g_part[B_];
__device__ __align__(16) float g_wt[104 * 912];        // W: [f(104)][kk=dlt*304+e (912)], tf32-rounded
__device__ unsigned g_cnt;                             // last-block counter (self-resetting)

// ---- packed fp32x2 helpers (sm_103a) ----
#define PACK2(d, lo, hi) \
    asm("mov.b64 %0, {%1, %2};" : "=l"(d) : "r"(__float_as_uint(lo)), "r"(__float_as_uint(hi)))
#define FMA2(d, a, b) \
    asm("fma.rn.f32x2 %0, %1, %2, %0;" : "+l"(d) : "l"(a), "l"(b))
#define MUL2(d, a, b) \
    asm("mul.rn.f32x2 %0, %1, %2;" : "=l"(d) : "l"(a), "l"(b))
#define UNPACK2(lo, hi, v) do { unsigned _l, _h; \
    asm("mov.b64 {%0, %1}, %2;" : "=r"(_l), "=r"(_h) : "l"(v)); \
    lo = __uint_as_float(_l); hi = __uint_as_float(_h); } while (0)

// tf32 round-to-nearest (rna), result in low-precision-safe f32 register
__device__ __forceinline__ float to_tf32(float x) {
    float r;
    asm("cvt.rna.tf32.f32 %0, %1;" : "=f"(r) : "f"(x));
    return r;
}

// m16n8k4 tf32 MMA (legacy HMMA path, sm_80+ incl. sm_103a).
// A: a0 row=lane/4, a1 row=lane/4+8, col=lane%4. B: b0 row(k)=lane%4, col(n)=lane/4.
// D: c0,c1 row=lane/4 cols 2(lane%4)+{0,1}; c2,c3 row=lane/4+8.
#define MMA_TF32_K4(d, a0, a1, bb) \
    asm("mma.sync.aligned.m16n8k4.row.col.f32.tf32.tf32.f32 " \
        "{%0,%1,%2,%3}, {%4,%5}, {%6}, {%0,%1,%2,%3};" \
        : "+f"(d[0]), "+f"(d[1]), "+f"(d[2]), "+f"(d[3]) \
        : "r"(a0), "r"(a1), "r"(bb))

// ---------------------------------------------------------------------------
// Kernel 0: repack conv_w [F][E][3] -> g_wt[f][dlt*304+e], tf32-rounded, zero-pad
// ---------------------------------------------------------------------------
__global__ void k_wt(const float* __restrict__ cw)
{
    int i = blockIdx.x * 256 + threadIdx.x;
    if (i < 104 * 912) {
        int f = i / 912, kk = i - f * 912;
        int dlt = kk / 304, e = kk - dlt * 304;
        float v = 0.f;
        if (f < F_ && e < E_) v = to_tf32(__ldg(&cw[f * 900 + e * 3 + dlt]));
        g_wt[i] = v;
    }
}

__global__ void k_nop() {}

// ---------------------------------------------------------------------------
// Kernel 1: emb gather + conv1d(K=3,pad=1) via tf32 tensor-core GEMM + ReLU + FC
// Block: 128 threads (4 warps), 64 s-positions of one batch row. grid (8, 32).
// Conv GEMM: H[64,104] = A[64,912] x W[912,104]; A rows for shift dlt are the
// emb smem tile read at row offset dlt (66 halo rows). Warp w owns rows 16w..16w+15,
// all 104 f (13 n8 tiles, 52 fp32 accum regs). E chunked by 16 (19 chunks).
// ---------------------------------------------------------------------------
__global__ __launch_bounds__(128) void k_emissions(
    const int* __restrict__ x,
    const float* __restrict__ emb,
    const float* __restrict__ conv_b,
    const float* __restrict__ fc_w,     // [T,F]
    const float* __restrict__ fc_b)
{
    // phase1: sT[66][20] @0 (1320) | Wt[104][52] @1320 (5408)
    // phase2: feat[64][106] @0 (6784) | fcwT[100][52] @6784 (5200)
    __shared__ __align__(16) float sbuf[11984];   // 47.9 KB
    __shared__ int sx[66];

    const int tid  = threadIdx.x;
    const int b    = blockIdx.y;
    const int s0   = blockIdx.x * 64;
    const int lane = tid & 31;
    const int w    = tid >> 5;
    const int m0   = w * 16;
    const int gq   = lane >> 2;     // groupID (0..7)
    const int tq   = lane & 3;      // threadID_in_group (0..3)

    float* sT   = sbuf;             // stride 20 (20 mod 32 = 20, conflict-free over gq)
    float* Wt   = sbuf + 1320;      // stride 52 (52 mod 32 = 20, conflict-free over gq)
    float* feat = sbuf;             // stride 106
    float* fcwT = sbuf + 6784;      // stride 52

    if (tid < 66) {
        int sg = s0 - 1 + tid;
        sx[tid] = (sg >= 0 && sg < S_) ? x[b * S_ + sg] : -1;
    }

    float acc[13][4];
    #pragma unroll
    for (int n = 0; n < 13; n++)
        #pragma unroll
        for (int q = 0; q < 4; q++) acc[n][q] = 0.f;

    for (int c = 0; c < 19; c++) {
        const int e0 = c * 16;
        __syncthreads();   // previous chunk's reads complete (covers sx init on c=0)
        // stage emb chunk: sT[r][el] = tf32(emb[sx[r]][e0+el])
        for (int idx = tid; idx < 66 * 16; idx += 128) {
            int r = idx >> 4, el = idx & 15;
            int v = sx[r];
            float val = 0.f;
            if (v >= 0 && e0 + el < E_) val = to_tf32(__ldg(&emb[v * E_ + e0 + el]));
            sT[r * 20 + el] = val;
        }
        // stage W chunk: Wt[f][dlt*16+q] from g_wt[f][dlt*304+e0+q]
        for (int idx = tid; idx < 1248; idx += 128) {
            int f = idx / 12, rem = idx - f * 12;
            int dlt = rem >> 2, q4 = (rem & 3) * 4;
            float4 wv = *(const float4*)&g_wt[f * 912 + dlt * 304 + e0 + q4];
            *(float4*)&Wt[f * 52 + dlt * 16 + q4] = wv;
        }
        __syncthreads();
        #pragma unroll
        for (int dlt = 0; dlt < 3; dlt++) {
            #pragma unroll
            for (int e4 = 0; e4 < 4; e4++) {
                const int el = 4 * e4 + tq;
                unsigned a0 = __float_as_uint(sT[(m0 + dlt + gq)     * 20 + el]);
                unsigned a1 = __float_as_uint(sT[(m0 + dlt + gq + 8) * 20 + el]);
                const int kkl = dlt * 16 + 4 * e4 + tq;
                #pragma unroll
                for (int n = 0; n < 13; n++) {
                    unsigned bb = __float_as_uint(Wt[(8 * n + gq) * 52 + kkl]);
                    MMA_TF32_K4(acc[n], a0, a1, bb);
                }
            }
        }
    }
    __syncthreads();   // all reads of sT/Wt done -> reuse region as feat

    // epilogue: bias + ReLU -> feat (f >= 100 lands in cols 100..103, unused by FC)
    #pragma unroll
    for (int n = 0; n < 13; n++) {
        int f = 8 * n + 2 * tq;
        float b0v = (f     < F_) ? __ldg(&conv_b[f])     : 0.f;
        float b1v = (f + 1 < F_) ? __ldg(&conv_b[f + 1]) : 0.f;
        int r0 = m0 + gq, r1 = m0 + gq + 8;
        feat[r0 * 106 + f]     = fmaxf(acc[n][0] + b0v, 0.f);
        feat[r0 * 106 + f + 1] = fmaxf(acc[n][1] + b1v, 0.f);
        feat[r1 * 106 + f]     = fmaxf(acc[n][2] + b0v, 0.f);
        feat[r1 * 106 + f + 1] = fmaxf(acc[n][3] + b1v, 0.f);
    }
    // stage fc_w transposed [f][t] stride 52
    for (int idx = tid; idx < T_ * F_; idx += 128) {
        int t = idx / F_, f = idx - t * F_;
        fcwT[f * 52 + t] = __ldg(&fc_w[idx]);
    }
    __syncthreads();

    // FC: em[s][t] = feat[s][0:100] . fc_w[t][:] + fc_b[t]   (full fp32)
    for (int idx = tid; idx < 64 * T_; idx += 128) {
        int s = idx / T_, t = idx - s * T_;
        float d = __ldg(&fc_b[t]);
        const float* fv = feat + s * 106;
        const float* fw = fcwT + t;
        #pragma unroll 10
        for (int f = 0; f < F_; f++) d += fv[f] * fw[f * 52];
        g_em[(b * S_ + (s0 + s)) * T_ + t] = d;
    }
}

// ---------------------------------------------------------------------------
// Kernel 2: CRF, single warp per batch, linear domain, shuffle-broadcast matvec.
// ---------------------------------------------------------------------------
__global__ __launch_bounds__(32) void k_crf(
    const int* __restrict__ tags,
    const float* __restrict__ start_trans,
    const float* __restrict__ end_trans,
    const float* __restrict__ trans,
    float* __restrict__ out)
{
    const int tid  = threadIdx.x;
    const int b    = blockIdx.x;
    const int base = b * S_;
    const bool act = (tid < 25);
    const int j0 = 2 * tid, j1 = 2 * tid + 1;

    uint64_t Ej0[25], Ej1[25];
    if (act) {
        #pragma unroll
        for (int i = 0; i < 25; i++) {
            float e00 = __expf(__ldg(&trans[(2 * i)     * T_ + j0]));
            float e01 = __expf(__ldg(&trans[(2 * i + 1) * T_ + j0]));
            float e10 = __expf(__ldg(&trans[(2 * i)     * T_ + j1]));
            float e11 = __expf(__ldg(&trans[(2 * i + 1) * T_ + j1]));
            PACK2(Ej0[i], e00, e01);
            PACK2(Ej1[i], e10, e11);
        }
    } else {
        #pragma unroll
        for (int i = 0; i < 25; i++) { Ej0[i] = 0ull; Ej1[i] = 0ull; }
    }

    // numerator: gold path score
    const int* tg = tags + base;
    float local = 0.f;
    for (int s = tid; s < S_; s += 32) {
        int t = __ldg(&tg[s]);
        local += __ldg(&g_em[(base + s) * T_ + t]);
        if (s < S_ - 1) local += __ldg(&trans[t * T_ + __ldg(&tg[s + 1])]);
    }
    #pragma unroll
    for (int o = 16; o; o >>= 1) local += __shfl_xor_sync(0xffffffffu, local, o);
    float s_num = local + __ldg(&start_trans[tg[0]]) + __ldg(&end_trans[tg[S_ - 1]]);

    // init alpha (log -> linear with offset)
    float al0 = -3.0e38f, al1 = -3.0e38f;
    if (act) {
        float2 e0 = *(const float2*)&g_em[base * T_ + j0];
        al0 = __ldg(&start_trans[j0]) + e0.x;
        al1 = __ldg(&start_trans[j1]) + e0.y;
    }
    float mv = fmaxf(al0, al1);
    #pragma unroll
    for (int o = 16; o; o >>= 1) mv = fmaxf(mv, __shfl_xor_sync(0xffffffffu, mv, o));
    float off = mv;
    uint64_t apk = 0ull;
    if (act) { PACK2(apk, __expf(al0 - mv), __expf(al1 - mv)); }

    // forward scan: 63 groups of 8 (s=1..504) + partial of 7
    float2 bufA[8], bufB[8];
    #pragma unroll
    for (int k = 0; k < 8; k++) { bufA[k] = make_float2(0.f, 0.f); bufB[k] = make_float2(0.f, 0.f); }
    if (act) {
        #pragma unroll
        for (int k = 0; k < 8; k++)
            bufA[k] = __ldg((const float2*)&g_em[(base + 1 + k) * T_ + j0]);
    }

    for (int g = 0; g < 64; g++) {
        if (g < 63 && act) {
            int sn = 8 * g + 9;
            #pragma unroll
            for (int k = 0; k < 8; k++)
                if (sn + k < S_) bufB[k] = __ldg((const float2*)&g_em[(base + sn + k) * T_ + j0]);
        }
        uint64_t eem[8];
        #pragma unroll
        for (int k = 0; k < 8; k++) {
            float e0 = __expf(bufA[k].x), e1 = __expf(bufA[k].y);
            PACK2(eem[k], e0, e1);
        }
        const int nst = (g < 63) ? 8 : 7;
        #pragma unroll
        for (int k = 0; k < 8; k++) {
            if (k >= nst) break;
            uint64_t d00 = 0ull, d01 = 0ull, d10 = 0ull, d11 = 0ull;
            #pragma unroll
            for (int i = 0; i < 25; i++) {
                uint64_t pv = __shfl_sync(0xffffffffu, apk, i);
                if (i & 1) { FMA2(d01, pv, Ej0[i]); FMA2(d11, pv, Ej1[i]); }
                else       { FMA2(d00, pv, Ej0[i]); FMA2(d10, pv, Ej1[i]); }
            }
            float l, h;
            UNPACK2(l, h, d00); float sm0 = l + h;
            UNPACK2(l, h, d01); sm0 += l + h;
            UNPACK2(l, h, d10); float sm1 = l + h;
            UNPACK2(l, h, d11); sm1 += l + h;
            uint64_t sp;
            PACK2(sp, sm0, sm1);
            MUL2(apk, sp, eem[k]);   // inactive lanes: Ej=0 -> apk stays 0
        }
        if (g < 63) {
            float a0, a1;
            UNPACK2(a0, a1, apk);
            float m = fmaxf(a0, a1);
            #pragma unroll
            for (int o = 16; o; o >>= 1) m = fmaxf(m, __shfl_xor_sync(0xffffffffu, m, o));
            float inv = 1.0f / m;
            off += __logf(m);
            uint64_t ip; PACK2(ip, inv, inv);
            MUL2(apk, apk, ip);
        }
        #pragma unroll
        for (int k = 0; k < 8; k++) bufA[k] = bufB[k];
    }

    // log_z
    float av = 0.f;
    if (act) {
        float a0, a1; UNPACK2(a0, a1, apk);
        av = a0 * __expf(__ldg(&end_trans[j0])) + a1 * __expf(__ldg(&end_trans[j1]));
    }
    #pragma unroll
    for (int o = 16; o; o >>= 1) av += __shfl_xor_sync(0xffffffffu, av, o);
    if (tid == 0) g_part[b] = (off + logf(av)) - s_num;

    // last block reduces g_part -> out, resets counter
    unsigned isl = 0;
    if (tid == 0) {
        __threadfence();
        unsigned prev = atomicAdd(&g_cnt, 1u);
        isl = (prev == B_ - 1) ? 1u : 0u;
    }
    isl = __shfl_sync(0xffffffffu, isl, 0);
    if (isl) {
        __threadfence();
        float v = g_part[tid];
        #pragma unroll
        for (int o = 16; o; o >>= 1) v += __shfl_xor_sync(0xffffffffu, v, o);
        if (tid == 0) { out[0] = v; g_cnt = 0u; }
    }
}

extern "C" void kernel_launch(void* const* d_in, const int* in_sizes, int n_in,
                              void* d_out, int out_size)
{
    const int*   x           = (const int*)  d_in[0];
    const int*   tags        = (const int*)  d_in[1];
    const float* emb         = (const float*)d_in[2];
    const float* conv_w      = (const float*)d_in[3];
    const float* conv_b      = (const float*)d_in[4];
    const float* fc_w        = (const float*)d_in[5];
    const float* fc_b        = (const float*)d_in[6];
    const float* start_trans = (const float*)d_in[7];
    const float* end_trans   = (const float*)d_in[8];
    const float* trans       = (const float*)d_in[9];
    float* out = (float*)d_out;

    k_wt<<<(104 * 912 + 255) / 256, 256>>>(conv_w);
    // two nops so ncu's fixed capture (replay launch index 3) lands on k_emissions
    k_nop<<<1, 1>>>();
    k_nop<<<1, 1>>>();
    k_emissions<<<dim3(S_ / 64, B_), 128>>>(x, emb, conv_b, fc_w, fc_b);
    k_crf<<<B_, 32>>>(tags, start_trans, end_trans, trans, out);
}

// round 6
// speedup vs baseline: 2.0887x; 1.3320x over previous
#include <cuda_runtime.h>
#include <math.h>
#include <stdint.h>

#define B_ 32
#define S_ 512
#define E_ 300
#define F_ 100
#define T_ 50
#define NCH 38            // e-chunks of 8 (covers 304 e, zero-padded)
#define WTC 2496          // 104 f x 24 k floats per W chunk

// Scratch (no allocations allowed)
__device__ float g_em[B_ * S_ * T_];                 // emissions [B,S,T]
__device__ float g_part[B_];
__device__ __align__(16) float g_wt2[NCH * WTC];     // conv W: [chunk][f(104)][dlt*8+perm(el)]
__device__ __align__(16) float g_fcw[56 * 104];      // fc W: [t(56)][permuted f(104)]
__device__ unsigned g_cnt;

// ---- packed fp32x2 helpers (CRF) ----
#define PACK2(d, lo, hi) \
    asm("mov.b64 %0, {%1, %2};" : "=l"(d) : "r"(__float_as_uint(lo)), "r"(__float_as_uint(hi)))
#define FMA2(d, a, b) \
    asm("fma.rn.f32x2 %0, %1, %2, %0;" : "+l"(d) : "l"(a), "l"(b))
#define MUL2(d, a, b) \
    asm("mul.rn.f32x2 %0, %1, %2;" : "=l"(d) : "l"(a), "l"(b))
#define UNPACK2(lo, hi, v) do { unsigned _l, _h; \
    asm("mov.b64 {%0, %1}, %2;" : "=r"(_l), "=r"(_h) : "l"(v)); \
    lo = __uint_as_float(_l); hi = __uint_as_float(_h); } while (0)

__device__ __forceinline__ float to_tf32(float x) {
    float r;
    asm("cvt.rna.tf32.f32 %0, %1;" : "=f"(r) : "f"(x));
    return r;
}
// within-8 k permutation: logical k -> stored k' = 2*(k%4) + k/4
// => logical cols (tq, tq+4) are stored adjacent at (2tq, 2tq+1): one LDS.64 per fragment pair
__device__ __forceinline__ int permk(int el) { return 2 * (el & 3) + (el >> 2); }

// m16n8k8 tf32 MMA. A: a0(r=gq,c=tq) a1(r=gq+8,c=tq) a2(r=gq,c=tq+4) a3(r=gq+8,c=tq+4)
// B: b0(k=tq,n=gq) b1(k=tq+4,n=gq). D: c0(gq,2tq) c1(gq,2tq+1) c2(gq+8,2tq) c3(gq+8,2tq+1)
#define MMA_TF32_K8(d, a0, a1, a2, a3, b0, b1) \
    asm("mma.sync.aligned.m16n8k8.row.col.f32.tf32.tf32.f32 " \
        "{%0,%1,%2,%3}, {%4,%5,%6,%7}, {%8,%9}, {%0,%1,%2,%3};" \
        : "+f"(d[0]), "+f"(d[1]), "+f"(d[2]), "+f"(d[3]) \
        : "r"(a0), "r"(a1), "r"(a2), "r"(a3), "r"(b0), "r"(b1))

__global__ void k_nop() {}

// ---------------------------------------------------------------------------
// Kernel 0: prepack conv_w -> g_wt2 (chunked, permuted, tf32, zero-pad) and
// fc_w -> g_fcw ([t][perm f], tf32, zero-pad)
// ---------------------------------------------------------------------------
__global__ void k_wt(const float* __restrict__ cw, const float* __restrict__ fw)
{
    int i = blockIdx.x * 256 + threadIdx.x;
    if (i < NCH * WTC) {
        int c = i / WTC, r = i - c * WTC;
        int f = r / 24, kk = r - f * 24;
        int dlt = kk >> 3, kp = kk & 7;
        int el = (kp >> 1) + 4 * (kp & 1);       // invert permk
        int e = c * 8 + el;
        float v = 0.f;
        if (f < F_ && e < E_) v = to_tf32(__ldg(&cw[f * 900 + e * 3 + dlt]));
        g_wt2[i] = v;
    }
    int j = i - NCH * WTC;
    if (j >= 0 && j < 56 * 104) {
        int t = j / 104, kf = j - t * 104;
        int g8 = kf >> 3, kp = kf & 7;
        int f = g8 * 8 + (kp >> 1) + 4 * (kp & 1);
        float v = 0.f;
        if (t < T_ && f < F_) v = to_tf32(__ldg(&fw[t * F_ + f]));
        g_fcw[j] = v;
    }
}

// ---------------------------------------------------------------------------
// Kernel 1: emb gather + conv1d(K=3,pad=1) GEMM + ReLU + FC GEMM -> emissions
// 256 threads (8 warps), 64 s per block, grid (8, 32). Double-buffered e-chunks
// of 8. Conv: warps 0-3 m-tile w / n-tiles 0-6; warps 4-7 m-tile w-4 / n 7-12.
// FC: m-tile w&3; warps 0-3 n 0-3, warps 4-7 n 4-6. All frags via LDS.64.
// ---------------------------------------------------------------------------
__global__ __launch_bounds__(256, 2) void k_emissions(
    const int* __restrict__ x,
    const float* __restrict__ emb,
    const float* __restrict__ conv_b,
    const float* __restrict__ fc_b)
{
    // buffers: buf k at k*3024: sT[66][8] (528) + Wt[104][24] (2496)
    // phase2: feat[64][104] at 0 (6656)
    __shared__ __align__(16) float sbuf[6656];
    __shared__ int sx[66];

    const int tid  = threadIdx.x;
    const int b    = blockIdx.y;
    const int s0   = blockIdx.x * 64;
    const int lane = tid & 31;
    const int w    = tid >> 5;
    const int gq   = lane >> 2;
    const int tq   = lane & 3;

    if (tid < 66) {
        int sg = s0 - 1 + tid;
        sx[tid] = (sg >= 0 && sg < S_) ? x[b * S_ + sg] : -1;
    }
    __syncthreads();

    // stage chunk 0 into buf0
    for (int idx = tid; idx < 528; idx += 256) {
        int r = idx >> 3, el = idx & 7, v = sx[r];
        sbuf[r * 8 + permk(el)] = (v >= 0) ? to_tf32(__ldg(&emb[v * E_ + el])) : 0.f;
    }
    for (int idx = tid; idx < 624; idx += 256)
        *(float4*)&sbuf[528 + idx * 4] = *(const float4*)&g_wt2[idx * 4];
    __syncthreads();

    const int m0     = 16 * (w & 3);
    const int nbase  = (w < 4) ? 0 : 7;
    const int ntiles = (w < 4) ? 7 : 6;

    float acc[7][4];
    #pragma unroll
    for (int n = 0; n < 7; n++)
        #pragma unroll
        for (int q = 0; q < 4; q++) acc[n][q] = 0.f;

    float  pa[3];
    float4 pw[3];
    for (int c = 0; c < NCH; c++) {
        float* sT = sbuf + (c & 1) * 3024;
        float* Wt = sT + 528;
        if (c + 1 < NCH) {   // prefetch next chunk into registers
            int e0 = (c + 1) * 8;
            #pragma unroll
            for (int r3 = 0; r3 < 3; r3++) {
                int idx = tid + 256 * r3;
                pa[r3] = 0.f;
                if (idx < 528) {
                    int v = sx[idx >> 3], e = e0 + (idx & 7);
                    if (v >= 0 && e < E_) pa[r3] = to_tf32(__ldg(&emb[v * E_ + e]));
                }
            }
            const float4* wsrc = (const float4*)&g_wt2[(c + 1) * WTC];
            #pragma unroll
            for (int r3 = 0; r3 < 3; r3++) {
                int idx = tid + 256 * r3;
                if (idx < 624) pw[r3] = __ldg(&wsrc[idx]);
            }
        }
        // MMA on current buffer: 3 dlt x (1 k8-step each) x n-tiles
        #pragma unroll
        for (int dlt = 0; dlt < 3; dlt++) {
            float2 aLo = *(const float2*)&sT[(m0 + dlt + gq)     * 8 + 2 * tq];
            float2 aHi = *(const float2*)&sT[(m0 + dlt + gq + 8) * 8 + 2 * tq];
            unsigned a0 = __float_as_uint(aLo.x), a2 = __float_as_uint(aLo.y);
            unsigned a1 = __float_as_uint(aHi.x), a3 = __float_as_uint(aHi.y);
            #pragma unroll
            for (int n = 0; n < 7; n++) {
                if (n < ntiles) {
                    float2 bb = *(const float2*)&Wt[(8 * (nbase + n) + gq) * 24 + dlt * 8 + 2 * tq];
                    MMA_TF32_K8(acc[n], a0, a1, a2, a3,
                                __float_as_uint(bb.x), __float_as_uint(bb.y));
                }
            }
        }
        __syncthreads();
        if (c + 1 < NCH) {   // store prefetched chunk to other buffer
            float* sTn = sbuf + ((c + 1) & 1) * 3024;
            float* Wtn = sTn + 528;
            #pragma unroll
            for (int r3 = 0; r3 < 3; r3++) {
                int idx = tid + 256 * r3;
                if (idx < 528) sTn[(idx >> 3) * 8 + permk(idx & 7)] = pa[r3];
            }
            #pragma unroll
            for (int r3 = 0; r3 < 3; r3++) {
                int idx = tid + 256 * r3;
                if (idx < 624) *(float4*)&Wtn[idx * 4] = pw[r3];
            }
        }
        __syncthreads();
    }

    // conv epilogue: bias + ReLU + tf32-round -> feat[64][104] (k-permuted cols)
    float* feat = sbuf;
    #pragma unroll
    for (int n = 0; n < 7; n++) {
        if (n < ntiles) {
            int f = 8 * (nbase + n) + 2 * tq;
            float b0v = (f     < F_) ? __ldg(&conv_b[f])     : 0.f;
            float b1v = (f + 1 < F_) ? __ldg(&conv_b[f + 1]) : 0.f;
            int k0 = (f >> 3) * 8 + permk(f & 7);
            int k1 = ((f + 1) >> 3) * 8 + permk((f + 1) & 7);
            feat[(m0 + gq)     * 104 + k0] = to_tf32(fmaxf(acc[n][0] + b0v, 0.f));
            feat[(m0 + gq)     * 104 + k1] = to_tf32(fmaxf(acc[n][1] + b1v, 0.f));
            feat[(m0 + gq + 8) * 104 + k0] = to_tf32(fmaxf(acc[n][2] + b0v, 0.f));
            feat[(m0 + gq + 8) * 104 + k1] = to_tf32(fmaxf(acc[n][3] + b1v, 0.f));
        }
    }
    __syncthreads();

    // FC GEMM: em[64 x 50] = feat[64 x 104] . g_fcw^T, fp32 accum
    const int mt  = w & 3;
    const int nb2 = (w < 4) ? 0 : 4;
    const int nt2 = (w < 4) ? 4 : 3;
    float fa[4][4];
    #pragma unroll
    for (int n = 0; n < 4; n++)
        #pragma unroll
        for (int q = 0; q < 4; q++) fa[n][q] = 0.f;

    #pragma unroll
    for (int kb = 0; kb < 13; kb++) {
        float2 aLo = *(const float2*)&feat[(mt * 16 + gq)     * 104 + kb * 8 + 2 * tq];
        float2 aHi = *(const float2*)&feat[(mt * 16 + gq + 8) * 104 + kb * 8 + 2 * tq];
        unsigned a0 = __float_as_uint(aLo.x), a2 = __float_as_uint(aLo.y);
        unsigned a1 = __float_as_uint(aHi.x), a3 = __float_as_uint(aHi.y);
        #pragma unroll
        for (int n = 0; n < 4; n++) {
            if (n < nt2) {
                float2 bb = __ldg((const float2*)&g_fcw[(8 * (nb2 + n) + gq) * 104 + kb * 8 + 2 * tq]);
                MMA_TF32_K8(fa[n], a0, a1, a2, a3,
                            __float_as_uint(bb.x), __float_as_uint(bb.y));
            }
        }
    }
    #pragma unroll
    for (int n = 0; n < 4; n++) {
        if (n < nt2) {
            int t = 8 * (nb2 + n) + 2 * tq;
            if (t < T_) {
                float bb0 = __ldg(&fc_b[t]), bb1 = __ldg(&fc_b[t + 1]);
                int s1 = s0 + mt * 16 + gq;
                *(float2*)&g_em[(b * S_ + s1)     * T_ + t] =
                    make_float2(fa[n][0] + bb0, fa[n][1] + bb1);
                *(float2*)&g_em[(b * S_ + s1 + 8) * T_ + t] =
                    make_float2(fa[n][2] + bb0, fa[n][3] + bb1);
            }
        }
    }
}

// ---------------------------------------------------------------------------
// Kernel 2: CRF, single warp per batch, linear domain, shuffle-broadcast matvec.
// ---------------------------------------------------------------------------
__global__ __launch_bounds__(32) void k_crf(
    const int* __restrict__ tags,
    const float* __restrict__ start_trans,
    const float* __restrict__ end_trans,
    const float* __restrict__ trans,
    float* __restrict__ out)
{
    const int tid  = threadIdx.x;
    const int b    = blockIdx.x;
    const int base = b * S_;
    const bool act = (tid < 25);
    const int j0 = 2 * tid, j1 = 2 * tid + 1;

    uint64_t Ej0[25], Ej1[25];
    if (act) {
        #pragma unroll
        for (int i = 0; i < 25; i++) {
            float e00 = __expf(__ldg(&trans[(2 * i)     * T_ + j0]));
            float e01 = __expf(__ldg(&trans[(2 * i + 1) * T_ + j0]));
            float e10 = __expf(__ldg(&trans[(2 * i)     * T_ + j1]));
            float e11 = __expf(__ldg(&trans[(2 * i + 1) * T_ + j1]));
            PACK2(Ej0[i], e00, e01);
            PACK2(Ej1[i], e10, e11);
        }
    } else {
        #pragma unroll
        for (int i = 0; i < 25; i++) { Ej0[i] = 0ull; Ej1[i] = 0ull; }
    }

    // numerator: gold path score
    const int* tg = tags + base;
    float local = 0.f;
    for (int s = tid; s < S_; s += 32) {
        int t = __ldg(&tg[s]);
        local += __ldg(&g_em[(base + s) * T_ + t]);
        if (s < S_ - 1) local += __ldg(&trans[t * T_ + __ldg(&tg[s + 1])]);
    }
    #pragma unroll
    for (int o = 16; o; o >>= 1) local += __shfl_xor_sync(0xffffffffu, local, o);
    float s_num = local + __ldg(&start_trans[tg[0]]) + __ldg(&end_trans[tg[S_ - 1]]);

    // init alpha (log -> linear with offset)
    float al0 = -3.0e38f, al1 = -3.0e38f;
    if (act) {
        float2 e0 = *(const float2*)&g_em[base * T_ + j0];
        al0 = __ldg(&start_trans[j0]) + e0.x;
        al1 = __ldg(&start_trans[j1]) + e0.y;
    }
    float mv = fmaxf(al0, al1);
    #pragma unroll
    for (int o = 16; o; o >>= 1) mv = fmaxf(mv, __shfl_xor_sync(0xffffffffu, mv, o));
    float off = mv;
    uint64_t apk = 0ull;
    if (act) { PACK2(apk, __expf(al0 - mv), __expf(al1 - mv)); }

    // forward scan: 63 groups of 8 (s=1..504) + partial of 7
    float2 bufA[8], bufB[8];
    #pragma unroll
    for (int k = 0; k < 8; k++) { bufA[k] = make_float2(0.f, 0.f); bufB[k] = make_float2(0.f, 0.f); }
    if (act) {
        #pragma unroll
        for (int k = 0; k < 8; k++)
            bufA[k] = __ldg((const float2*)&g_em[(base + 1 + k) * T_ + j0]);
    }

    for (int g = 0; g < 64; g++) {
        if (g < 63 && act) {
            int sn = 8 * g + 9;
            #pragma unroll
            for (int k = 0; k < 8; k++)
                if (sn + k < S_) bufB[k] = __ldg((const float2*)&g_em[(base + sn + k) * T_ + j0]);
        }
        uint64_t eem[8];
        #pragma unroll
        for (int k = 0; k < 8; k++) {
            float e0 = __expf(bufA[k].x), e1 = __expf(bufA[k].y);
            PACK2(eem[k], e0, e1);
        }
        const int nst = (g < 63) ? 8 : 7;
        #pragma unroll
        for (int k = 0; k < 8; k++) {
            if (k >= nst) break;
            uint64_t d00 = 0ull, d01 = 0ull, d10 = 0ull, d11 = 0ull;
            #pragma unroll
            for (int i = 0; i < 25; i++) {
                uint64_t pv = __shfl_sync(0xffffffffu, apk, i);
                if (i & 1) { FMA2(d01, pv, Ej0[i]); FMA2(d11, pv, Ej1[i]); }
                else       { FMA2(d00, pv, Ej0[i]); FMA2(d10, pv, Ej1[i]); }
            }
            float l, h;
            UNPACK2(l, h, d00); float sm0 = l + h;
            UNPACK2(l, h, d01); sm0 += l + h;
            UNPACK2(l, h, d10); float sm1 = l + h;
            UNPACK2(l, h, d11); sm1 += l + h;
            uint64_t sp;
            PACK2(sp, sm0, sm1);
            MUL2(apk, sp, eem[k]);   // inactive lanes: Ej=0 -> apk stays 0
        }
        if (g < 63) {
            float a0, a1;
            UNPACK2(a0, a1, apk);
            float m = fmaxf(a0, a1);
            #pragma unroll
            for (int o = 16; o; o >>= 1) m = fmaxf(m, __shfl_xor_sync(0xffffffffu, m, o));
            float inv = 1.0f / m;
            off += __logf(m);
            uint64_t ip; PACK2(ip, inv, inv);
            MUL2(apk, apk, ip);
        }
        #pragma unroll
        for (int k = 0; k < 8; k++) bufA[k] = bufB[k];
    }

    // log_z
    float av = 0.f;
    if (act) {
        float a0, a1; UNPACK2(a0, a1, apk);
        av = a0 * __expf(__ldg(&end_trans[j0])) + a1 * __expf(__ldg(&end_trans[j1]));
    }
    #pragma unroll
    for (int o = 16; o; o >>= 1) av += __shfl_xor_sync(0xffffffffu, av, o);
    if (tid == 0) g_part[b] = (off + logf(av)) - s_num;

    // last block reduces g_part -> out, resets counter
    unsigned isl = 0;
    if (tid == 0) {
        __threadfence();
        unsigned prev = atomicAdd(&g_cnt, 1u);
        isl = (prev == B_ - 1) ? 1u : 0u;
    }
    isl = __shfl_sync(0xffffffffu, isl, 0);
    if (isl) {
        __threadfence();
        float v = g_part[tid];
        #pragma unroll
        for (int o = 16; o; o >>= 1) v += __shfl_xor_sync(0xffffffffu, v, o);
        if (tid == 0) { out[0] = v; g_cnt = 0u; }
    }
}

extern "C" void kernel_launch(void* const* d_in, const int* in_sizes, int n_in,
                              void* d_out, int out_size)
{
    const int*   x           = (const int*)  d_in[0];
    const int*   tags        = (const int*)  d_in[1];
    const float* emb         = (const float*)d_in[2];
    const float* conv_w      = (const float*)d_in[3];
    const float* conv_b      = (const float*)d_in[4];
    const float* fc_w        = (const float*)d_in[5];
    const float* fc_b        = (const float*)d_in[6];
    const float* start_trans = (const float*)d_in[7];
    const float* end_trans   = (const float*)d_in[8];
    const float* trans       = (const float*)d_in[9];
    float* out = (float*)d_out;

    // launch order: nop first so ncu's fixed capture (launch index 3) = k_crf
    k_nop<<<1, 1>>>();
    k_wt<<<(NCH * WTC + 56 * 104 + 255) / 256, 256>>>(conv_w, fc_w);
    k_emissions<<<dim3(S_ / 64, B_), 256>>>(x, emb, conv_b, fc_b);
    k_crf<<<B_, 32>>>(tags, start_trans, end_trans, trans, out);
}

// round 7
// speedup vs baseline: 2.3142x; 1.1079x over previous
#include <cuda_runtime.h>
#include <math.h>
#include <stdint.h>

#define B_ 32
#define S_ 512
#define E_ 300
#define F_ 100
#define T_ 50
#define NCH 38            // e-chunks of 8 (covers 304 e, zero-padded)
#define WTC 2496          // 104 f x 24 k floats per W chunk

// Scratch (no allocations allowed)
__device__ float g_em[B_ * S_ * T_];                 // emissions [B,S,T]
__device__ float g_part[B_];
__device__ __align__(16) float g_wt2[NCH * WTC];     // conv W: [chunk][f(104)][dlt*8+perm(el)]
__device__ __align__(16) float g_fcw[56 * 104];      // fc W: [t(56)][permuted f(104)]
__device__ unsigned g_cnt;

// ---- packed fp32x2 helpers ----
#define PACK2(d, lo, hi) \
    asm("mov.b64 %0, {%1, %2};" : "=l"(d) : "r"(__float_as_uint(lo)), "r"(__float_as_uint(hi)))
#define FMA2(d, a, b) \
    asm("fma.rn.f32x2 %0, %1, %2, %0;" : "+l"(d) : "l"(a), "l"(b))
#define MUL2(d, a, b) \
    asm("mul.rn.f32x2 %0, %1, %2;" : "=l"(d) : "l"(a), "l"(b))
#define UNPACK2(lo, hi, v) do { unsigned _l, _h; \
    asm("mov.b64 {%0, %1}, %2;" : "=r"(_l), "=r"(_h) : "l"(v)); \
    lo = __uint_as_float(_l); hi = __uint_as_float(_h); } while (0)

__device__ __forceinline__ float to_tf32(float x) {
    float r;
    asm("cvt.rna.tf32.f32 %0, %1;" : "=f"(r) : "f"(x));
    return r;
}
// within-8 k permutation: logical k -> stored k' = 2*(k%4) + k/4
__device__ __forceinline__ int permk(int el) { return 2 * (el & 3) + (el >> 2); }

// m16n8k8 tf32 MMA
#define MMA_TF32_K8(d, a0, a1, a2, a3, b0, b1) \
    asm("mma.sync.aligned.m16n8k8.row.col.f32.tf32.tf32.f32 " \
        "{%0,%1,%2,%3}, {%4,%5,%6,%7}, {%8,%9}, {%0,%1,%2,%3};" \
        : "+f"(d[0]), "+f"(d[1]), "+f"(d[2]), "+f"(d[3]) \
        : "r"(a0), "r"(a1), "r"(a2), "r"(a3), "r"(b0), "r"(b1))

__global__ void k_nop() {}

// ---------------------------------------------------------------------------
// Kernel 0: prepack conv_w -> g_wt2 and fc_w -> g_fcw (tf32, permuted, padded)
// ---------------------------------------------------------------------------
__global__ void k_wt(const float* __restrict__ cw, const float* __restrict__ fw)
{
    int i = blockIdx.x * 256 + threadIdx.x;
    if (i < NCH * WTC) {
        int c = i / WTC, r = i - c * WTC;
        int f = r / 24, kk = r - f * 24;
        int dlt = kk >> 3, kp = kk & 7;
        int el = (kp >> 1) + 4 * (kp & 1);       // invert permk
        int e = c * 8 + el;
        float v = 0.f;
        if (f < F_ && e < E_) v = to_tf32(__ldg(&cw[f * 900 + e * 3 + dlt]));
        g_wt2[i] = v;
    }
    int j = i - NCH * WTC;
    if (j >= 0 && j < 56 * 104) {
        int t = j / 104, kf = j - t * 104;
        int g8 = kf >> 3, kp = kf & 7;
        int f = g8 * 8 + (kp >> 1) + 4 * (kp & 1);
        float v = 0.f;
        if (t < T_ && f < F_) v = to_tf32(__ldg(&fw[t * F_ + f]));
        g_fcw[j] = v;
    }
}

// ---------------------------------------------------------------------------
// Kernel 1: emb gather + conv GEMM + ReLU + FC GEMM -> emissions (unchanged R6)
// ---------------------------------------------------------------------------
__global__ __launch_bounds__(256, 2) void k_emissions(
    const int* __restrict__ x,
    const float* __restrict__ emb,
    const float* __restrict__ conv_b,
    const float* __restrict__ fc_b)
{
    __shared__ __align__(16) float sbuf[6656];
    __shared__ int sx[66];

    const int tid  = threadIdx.x;
    const int b    = blockIdx.y;
    const int s0   = blockIdx.x * 64;
    const int lane = tid & 31;
    const int w    = tid >> 5;
    const int gq   = lane >> 2;
    const int tq   = lane & 3;

    if (tid < 66) {
        int sg = s0 - 1 + tid;
        sx[tid] = (sg >= 0 && sg < S_) ? x[b * S_ + sg] : -1;
    }
    __syncthreads();

    for (int idx = tid; idx < 528; idx += 256) {
        int r = idx >> 3, el = idx & 7, v = sx[r];
        sbuf[r * 8 + permk(el)] = (v >= 0) ? to_tf32(__ldg(&emb[v * E_ + el])) : 0.f;
    }
    for (int idx = tid; idx < 624; idx += 256)
        *(float4*)&sbuf[528 + idx * 4] = *(const float4*)&g_wt2[idx * 4];
    __syncthreads();

    const int m0     = 16 * (w & 3);
    const int nbase  = (w < 4) ? 0 : 7;
    const int ntiles = (w < 4) ? 7 : 6;

    float acc[7][4];
    #pragma unroll
    for (int n = 0; n < 7; n++)
        #pragma unroll
        for (int q = 0; q < 4; q++) acc[n][q] = 0.f;

    float  pa[3];
    float4 pw[3];
    for (int c = 0; c < NCH; c++) {
        float* sT = sbuf + (c & 1) * 3024;
        float* Wt = sT + 528;
        if (c + 1 < NCH) {
            int e0 = (c + 1) * 8;
            #pragma unroll
            for (int r3 = 0; r3 < 3; r3++) {
                int idx = tid + 256 * r3;
                pa[r3] = 0.f;
                if (idx < 528) {
                    int v = sx[idx >> 3], e = e0 + (idx & 7);
                    if (v >= 0 && e < E_) pa[r3] = to_tf32(__ldg(&emb[v * E_ + e]));
                }
            }
            const float4* wsrc = (const float4*)&g_wt2[(c + 1) * WTC];
            #pragma unroll
            for (int r3 = 0; r3 < 3; r3++) {
                int idx = tid + 256 * r3;
                if (idx < 624) pw[r3] = __ldg(&wsrc[idx]);
            }
        }
        #pragma unroll
        for (int dlt = 0; dlt < 3; dlt++) {
            float2 aLo = *(const float2*)&sT[(m0 + dlt + gq)     * 8 + 2 * tq];
            float2 aHi = *(const float2*)&sT[(m0 + dlt + gq + 8) * 8 + 2 * tq];
            unsigned a0 = __float_as_uint(aLo.x), a2 = __float_as_uint(aLo.y);
            unsigned a1 = __float_as_uint(aHi.x), a3 = __float_as_uint(aHi.y);
            #pragma unroll
            for (int n = 0; n < 7; n++) {
                if (n < ntiles) {
                    float2 bb = *(const float2*)&Wt[(8 * (nbase + n) + gq) * 24 + dlt * 8 + 2 * tq];
                    MMA_TF32_K8(acc[n], a0, a1, a2, a3,
                                __float_as_uint(bb.x), __float_as_uint(bb.y));
                }
            }
        }
        __syncthreads();
        if (c + 1 < NCH) {
            float* sTn = sbuf + ((c + 1) & 1) * 3024;
            float* Wtn = sTn + 528;
            #pragma unroll
            for (int r3 = 0; r3 < 3; r3++) {
                int idx = tid + 256 * r3;
                if (idx < 528) sTn[(idx >> 3) * 8 + permk(idx & 7)] = pa[r3];
            }
            #pragma unroll
            for (int r3 = 0; r3 < 3; r3++) {
                int idx = tid + 256 * r3;
                if (idx < 624) *(float4*)&Wtn[idx * 4] = pw[r3];
            }
        }
        __syncthreads();
    }

    float* feat = sbuf;
    #pragma unroll
    for (int n = 0; n < 7; n++) {
        if (n < ntiles) {
            int f = 8 * (nbase + n) + 2 * tq;
            float b0v = (f     < F_) ? __ldg(&conv_b[f])     : 0.f;
            float b1v = (f + 1 < F_) ? __ldg(&conv_b[f + 1]) : 0.f;
            int k0 = (f >> 3) * 8 + permk(f & 7);
            int k1 = ((f + 1) >> 3) * 8 + permk((f + 1) & 7);
            feat[(m0 + gq)     * 104 + k0] = to_tf32(fmaxf(acc[n][0] + b0v, 0.f));
            feat[(m0 + gq)     * 104 + k1] = to_tf32(fmaxf(acc[n][1] + b1v, 0.f));
            feat[(m0 + gq + 8) * 104 + k0] = to_tf32(fmaxf(acc[n][2] + b0v, 0.f));
            feat[(m0 + gq + 8) * 104 + k1] = to_tf32(fmaxf(acc[n][3] + b1v, 0.f));
        }
    }
    __syncthreads();

    const int mt  = w & 3;
    const int nb2 = (w < 4) ? 0 : 4;
    const int nt2 = (w < 4) ? 4 : 3;
    float fa[4][4];
    #pragma unroll
    for (int n = 0; n < 4; n++)
        #pragma unroll
        for (int q = 0; q < 4; q++) fa[n][q] = 0.f;

    #pragma unroll
    for (int kb = 0; kb < 13; kb++) {
        float2 aLo = *(const float2*)&feat[(mt * 16 + gq)     * 104 + kb * 8 + 2 * tq];
        float2 aHi = *(const float2*)&feat[(mt * 16 + gq + 8) * 104 + kb * 8 + 2 * tq];
        unsigned a0 = __float_as_uint(aLo.x), a2 = __float_as_uint(aLo.y);
        unsigned a1 = __float_as_uint(aHi.x), a3 = __float_as_uint(aHi.y);
        #pragma unroll
        for (int n = 0; n < 4; n++) {
            if (n < nt2) {
                float2 bb = __ldg((const float2*)&g_fcw[(8 * (nb2 + n) + gq) * 104 + kb * 8 + 2 * tq]);
                MMA_TF32_K8(fa[n], a0, a1, a2, a3,
                            __float_as_uint(bb.x), __float_as_uint(bb.y));
            }
        }
    }
    #pragma unroll
    for (int n = 0; n < 4; n++) {
        if (n < nt2) {
            int t = 8 * (nb2 + n) + 2 * tq;
            if (t < T_) {
                float bb0 = __ldg(&fc_b[t]), bb1 = __ldg(&fc_b[t + 1]);
                int s1 = s0 + mt * 16 + gq;
                *(float2*)&g_em[(b * S_ + s1)     * T_ + t] =
                    make_float2(fa[n][0] + bb0, fa[n][1] + bb1);
                *(float2*)&g_em[(b * S_ + s1 + 8) * T_ + t] =
                    make_float2(fa[n][2] + bb0, fa[n][3] + bb1);
            }
        }
    }
}

// ---------------------------------------------------------------------------
// Kernel 2: CRF, single warp per batch, linear domain.
// SHUFFLE-FREE matvec: lanes publish alpha via STS.64 into double-buffered
// pbuf; matvec reads p via 13 wide LDS (broadcast, conflict-free) on the LSU
// pipe, overlapping the 50 FMA2 on the fma pipe. One __syncwarp per step.
// ---------------------------------------------------------------------------
__global__ __launch_bounds__(32) void k_crf(
    const int* __restrict__ tags,
    const float* __restrict__ start_trans,
    const float* __restrict__ end_trans,
    const float* __restrict__ trans,
    float* __restrict__ out)
{
    __shared__ __align__(16) float pbuf[2][64];

    const int tid  = threadIdx.x;
    const int b    = blockIdx.x;
    const int base = b * S_;
    const bool act = (tid < 25);
    const int j0 = 2 * tid, j1 = 2 * tid + 1;

    // Ej0[i] = (E[2i][j0], E[2i+1][j0]); Ej1 same for j1
    uint64_t Ej0[25], Ej1[25];
    if (act) {
        #pragma unroll
        for (int i = 0; i < 25; i++) {
            float e00 = __expf(__ldg(&trans[(2 * i)     * T_ + j0]));
            float e01 = __expf(__ldg(&trans[(2 * i + 1) * T_ + j0]));
            float e10 = __expf(__ldg(&trans[(2 * i)     * T_ + j1]));
            float e11 = __expf(__ldg(&trans[(2 * i + 1) * T_ + j1]));
            PACK2(Ej0[i], e00, e01);
            PACK2(Ej1[i], e10, e11);
        }
    } else {
        #pragma unroll
        for (int i = 0; i < 25; i++) { Ej0[i] = 0ull; Ej1[i] = 0ull; }
    }

    // numerator: gold path score
    const int* tg = tags + base;
    float local = 0.f;
    for (int s = tid; s < S_; s += 32) {
        int t = __ldg(&tg[s]);
        local += __ldg(&g_em[(base + s) * T_ + t]);
        if (s < S_ - 1) local += __ldg(&trans[t * T_ + __ldg(&tg[s + 1])]);
    }
    #pragma unroll
    for (int o = 16; o; o >>= 1) local += __shfl_xor_sync(0xffffffffu, local, o);
    float s_num = local + __ldg(&start_trans[tg[0]]) + __ldg(&end_trans[tg[S_ - 1]]);

    // init alpha (log -> linear with offset)
    float al0 = -3.0e38f, al1 = -3.0e38f;
    if (act) {
        float2 e0 = *(const float2*)&g_em[base * T_ + j0];
        al0 = __ldg(&start_trans[j0]) + e0.x;
        al1 = __ldg(&start_trans[j1]) + e0.y;
    }
    float mv = fmaxf(al0, al1);
    #pragma unroll
    for (int o = 16; o; o >>= 1) mv = fmaxf(mv, __shfl_xor_sync(0xffffffffu, mv, o));
    float off = mv;
    uint64_t apk = 0ull;
    if (act) { PACK2(apk, __expf(al0 - mv), __expf(al1 - mv)); }

    // forward scan: 63 groups of 8 (s=1..504) + partial of 7
    float2 bufA[8], bufB[8];
    #pragma unroll
    for (int k = 0; k < 8; k++) { bufA[k] = make_float2(0.f, 0.f); bufB[k] = make_float2(0.f, 0.f); }
    if (act) {
        #pragma unroll
        for (int k = 0; k < 8; k++)
            bufA[k] = __ldg((const float2*)&g_em[(base + 1 + k) * T_ + j0]);
    }

    int bsel = 0;
    for (int g = 0; g < 64; g++) {
        if (g < 63 && act) {
            int sn = 8 * g + 9;
            #pragma unroll
            for (int k = 0; k < 8; k++)
                if (sn + k < S_) bufB[k] = __ldg((const float2*)&g_em[(base + sn + k) * T_ + j0]);
        }
        uint64_t eem[8];
        #pragma unroll
        for (int k = 0; k < 8; k++) {
            float e0 = __expf(bufA[k].x), e1 = __expf(bufA[k].y);
            PACK2(eem[k], e0, e1);
        }
        const int nst = (g < 63) ? 8 : 7;
        #pragma unroll
        for (int k = 0; k < 8; k++) {
            if (k >= nst) break;
            // publish alpha, then broadcast-read via wide LDS
            *(uint64_t*)&pbuf[bsel][2 * tid] = apk;
            __syncwarp();
            const ulonglong2* q2 = (const ulonglong2*)pbuf[bsel];
            uint64_t d00 = 0ull, d01 = 0ull, d10 = 0ull, d11 = 0ull;
            #pragma unroll
            for (int i = 0; i < 12; i++) {
                ulonglong2 q = q2[i];
                FMA2(d00, q.x, Ej0[2 * i]);     FMA2(d10, q.x, Ej1[2 * i]);
                FMA2(d01, q.y, Ej0[2 * i + 1]); FMA2(d11, q.y, Ej1[2 * i + 1]);
            }
            {
                uint64_t q = *(const uint64_t*)&pbuf[bsel][48];
                FMA2(d00, q, Ej0[24]); FMA2(d10, q, Ej1[24]);
            }
            float l, h;
            UNPACK2(l, h, d00); float sm0 = l + h;
            UNPACK2(l, h, d01); sm0 += l + h;
            UNPACK2(l, h, d10); float sm1 = l + h;
            UNPACK2(l, h, d11); sm1 += l + h;
            uint64_t sp;
            PACK2(sp, sm0, sm1);
            MUL2(apk, sp, eem[k]);   // inactive lanes: Ej=0 -> apk stays 0
            bsel ^= 1;
        }
        if (g < 63) {
            float a0, a1;
            UNPACK2(a0, a1, apk);
            float m = fmaxf(a0, a1);
            #pragma unroll
            for (int o = 16; o; o >>= 1) m = fmaxf(m, __shfl_xor_sync(0xffffffffu, m, o));
            float inv = 1.0f / m;
            off += __logf(m);
            uint64_t ip; PACK2(ip, inv, inv);
            MUL2(apk, apk, ip);
        }
        #pragma unroll
        for (int k = 0; k < 8; k++) bufA[k] = bufB[k];
    }

    // log_z
    float av = 0.f;
    if (act) {
        float a0, a1; UNPACK2(a0, a1, apk);
        av = a0 * __expf(__ldg(&end_trans[j0])) + a1 * __expf(__ldg(&end_trans[j1]));
    }
    #pragma unroll
    for (int o = 16; o; o >>= 1) av += __shfl_xor_sync(0xffffffffu, av, o);
    if (tid == 0) g_part[b] = (off + logf(av)) - s_num;

    // last block reduces g_part -> out, resets counter
    unsigned isl = 0;
    if (tid == 0) {
        __threadfence();
        unsigned prev = atomicAdd(&g_cnt, 1u);
        isl = (prev == B_ - 1) ? 1u : 0u;
    }
    isl = __shfl_sync(0xffffffffu, isl, 0);
    if (isl) {
        __threadfence();
        float v = g_part[tid];
        #pragma unroll
        for (int o = 16; o; o >>= 1) v += __shfl_xor_sync(0xffffffffu, v, o);
        if (tid == 0) { out[0] = v; g_cnt = 0u; }
    }
}

extern "C" void kernel_launch(void* const* d_in, const int* in_sizes, int n_in,
                              void* d_out, int out_size)
{
    const int*   x           = (const int*)  d_in[0];
    const int*   tags        = (const int*)  d_in[1];
    const float* emb         = (const float*)d_in[2];
    const float* conv_w      = (const float*)d_in[3];
    const float* conv_b      = (const float*)d_in[4];
    const float* fc_w        = (const float*)d_in[5];
    const float* fc_b        = (const float*)d_in[6];
    const float* start_trans = (const float*)d_in[7];
    const float* end_trans   = (const float*)d_in[8];
    const float* trans       = (const float*)d_in[9];
    float* out = (float*)d_out;

    // nop first: ncu's fixed capture (launch index 3) = k_crf
    k_nop<<<1, 1>>>();
    k_wt<<<(NCH * WTC + 56 * 104 + 255) / 256, 256>>>(conv_w, fc_w);
    k_emissions<<<dim3(S_ / 64, B_), 256>>>(x, emb, conv_b, fc_b);
    k_crf<<<B_, 32>>>(tags, start_trans, end_trans, trans, out);
}

// round 8
// speedup vs baseline: 2.3213x; 1.0031x over previous
#include <cuda_runtime.h>
#include <math.h>
#include <stdint.h>

#define B_ 32
#define S_ 512
#define E_ 300
#define F_ 100
#define T_ 50
#define NCH 38            // e-chunks of 8 (covers 304 e, zero-padded)
#define WTC 2496          // 104 f x 24 k floats per W chunk

// Scratch (no allocations allowed)
__device__ float g_em[B_ * S_ * T_];                 // emissions [B,S,T]
__device__ float g_part[B_];
__device__ __align__(16) float g_wt2[NCH * WTC];     // conv W: [chunk][f(104)][dlt*8+perm(el)]
__device__ __align__(16) float g_fcw[56 * 104];      // fc W: [t(56)][permuted f(104)]
__device__ unsigned g_cnt;

// ---- packed fp32x2 helpers ----
#define PACK2(d, lo, hi) \
    asm("mov.b64 %0, {%1, %2};" : "=l"(d) : "r"(__float_as_uint(lo)), "r"(__float_as_uint(hi)))
#define FMA2(d, a, b) \
    asm("fma.rn.f32x2 %0, %1, %2, %0;" : "+l"(d) : "l"(a), "l"(b))
#define MUL2(d, a, b) \
    asm("mul.rn.f32x2 %0, %1, %2;" : "=l"(d) : "l"(a), "l"(b))
#define UNPACK2(lo, hi, v) do { unsigned _l, _h; \
    asm("mov.b64 {%0, %1}, %2;" : "=r"(_l), "=r"(_h) : "l"(v)); \
    lo = __uint_as_float(_l); hi = __uint_as_float(_h); } while (0)

__device__ __forceinline__ float to_tf32(float x) {
    float r;
    asm("cvt.rna.tf32.f32 %0, %1;" : "=f"(r) : "f"(x));
    return r;
}
// within-8 k permutation: logical k -> stored k' = 2*(k%4) + k/4
__device__ __forceinline__ int permk(int el) { return 2 * (el & 3) + (el >> 2); }

// m16n8k8 tf32 MMA
#define MMA_TF32_K8(d, a0, a1, a2, a3, b0, b1) \
    asm("mma.sync.aligned.m16n8k8.row.col.f32.tf32.tf32.f32 " \
        "{%0,%1,%2,%3}, {%4,%5,%6,%7}, {%8,%9}, {%0,%1,%2,%3};" \
        : "+f"(d[0]), "+f"(d[1]), "+f"(d[2]), "+f"(d[3]) \
        : "r"(a0), "r"(a1), "r"(a2), "r"(a3), "r"(b0), "r"(b1))

__global__ void k_nop() {}

// ---------------------------------------------------------------------------
// Kernel 0: prepack conv_w -> g_wt2 and fc_w -> g_fcw (tf32, permuted, padded)
// ---------------------------------------------------------------------------
__global__ void k_wt(const float* __restrict__ cw, const float* __restrict__ fw)
{
    int i = blockIdx.x * 256 + threadIdx.x;
    if (i < NCH * WTC) {
        int c = i / WTC, r = i - c * WTC;
        int f = r / 24, kk = r - f * 24;
        int dlt = kk >> 3, kp = kk & 7;
        int el = (kp >> 1) + 4 * (kp & 1);       // invert permk
        int e = c * 8 + el;
        float v = 0.f;
        if (f < F_ && e < E_) v = to_tf32(__ldg(&cw[f * 900 + e * 3 + dlt]));
        g_wt2[i] = v;
    }
    int j = i - NCH * WTC;
    if (j >= 0 && j < 56 * 104) {
        int t = j / 104, kf = j - t * 104;
        int g8 = kf >> 3, kp = kf & 7;
        int f = g8 * 8 + (kp >> 1) + 4 * (kp & 1);
        float v = 0.f;
        if (t < T_ && f < F_) v = to_tf32(__ldg(&fw[t * F_ + f]));
        g_fcw[j] = v;
    }
}

// ---------------------------------------------------------------------------
// Kernel 1: emb gather + conv GEMM + ReLU + FC GEMM -> emissions (unchanged R6)
// ---------------------------------------------------------------------------
__global__ __launch_bounds__(256, 2) void k_emissions(
    const int* __restrict__ x,
    const float* __restrict__ emb,
    const float* __restrict__ conv_b,
    const float* __restrict__ fc_b)
{
    __shared__ __align__(16) float sbuf[6656];
    __shared__ int sx[66];

    const int tid  = threadIdx.x;
    const int b    = blockIdx.y;
    const int s0   = blockIdx.x * 64;
    const int lane = tid & 31;
    const int w    = tid >> 5;
    const int gq   = lane >> 2;
    const int tq   = lane & 3;

    if (tid < 66) {
        int sg = s0 - 1 + tid;
        sx[tid] = (sg >= 0 && sg < S_) ? x[b * S_ + sg] : -1;
    }
    __syncthreads();

    for (int idx = tid; idx < 528; idx += 256) {
        int r = idx >> 3, el = idx & 7, v = sx[r];
        sbuf[r * 8 + permk(el)] = (v >= 0) ? to_tf32(__ldg(&emb[v * E_ + el])) : 0.f;
    }
    for (int idx = tid; idx < 624; idx += 256)
        *(float4*)&sbuf[528 + idx * 4] = *(const float4*)&g_wt2[idx * 4];
    __syncthreads();

    const int m0     = 16 * (w & 3);
    const int nbase  = (w < 4) ? 0 : 7;
    const int ntiles = (w < 4) ? 7 : 6;

    float acc[7][4];
    #pragma unroll
    for (int n = 0; n < 7; n++)
        #pragma unroll
        for (int q = 0; q < 4; q++) acc[n][q] = 0.f;

    float  pa[3];
    float4 pw[3];
    for (int c = 0; c < NCH; c++) {
        float* sT = sbuf + (c & 1) * 3024;
        float* Wt = sT + 528;
        if (c + 1 < NCH) {
            int e0 = (c + 1) * 8;
            #pragma unroll
            for (int r3 = 0; r3 < 3; r3++) {
                int idx = tid + 256 * r3;
                pa[r3] = 0.f;
                if (idx < 528) {
                    int v = sx[idx >> 3], e = e0 + (idx & 7);
                    if (v >= 0 && e < E_) pa[r3] = to_tf32(__ldg(&emb[v * E_ + e]));
                }
            }
            const float4* wsrc = (const float4*)&g_wt2[(c + 1) * WTC];
            #pragma unroll
            for (int r3 = 0; r3 < 3; r3++) {
                int idx = tid + 256 * r3;
                if (idx < 624) pw[r3] = __ldg(&wsrc[idx]);
            }
        }
        #pragma unroll
        for (int dlt = 0; dlt < 3; dlt++) {
            float2 aLo = *(const float2*)&sT[(m0 + dlt + gq)     * 8 + 2 * tq];
            float2 aHi = *(const float2*)&sT[(m0 + dlt + gq + 8) * 8 + 2 * tq];
            unsigned a0 = __float_as_uint(aLo.x), a2 = __float_as_uint(aLo.y);
            unsigned a1 = __float_as_uint(aHi.x), a3 = __float_as_uint(aHi.y);
            #pragma unroll
            for (int n = 0; n < 7; n++) {
                if (n < ntiles) {
                    float2 bb = *(const float2*)&Wt[(8 * (nbase + n) + gq) * 24 + dlt * 8 + 2 * tq];
                    MMA_TF32_K8(acc[n], a0, a1, a2, a3,
                                __float_as_uint(bb.x), __float_as_uint(bb.y));
                }
            }
        }
        __syncthreads();
        if (c + 1 < NCH) {
            float* sTn = sbuf + ((c + 1) & 1) * 3024;
            float* Wtn = sTn + 528;
            #pragma unroll
            for (int r3 = 0; r3 < 3; r3++) {
                int idx = tid + 256 * r3;
                if (idx < 528) sTn[(idx >> 3) * 8 + permk(idx & 7)] = pa[r3];
            }
            #pragma unroll
            for (int r3 = 0; r3 < 3; r3++) {
                int idx = tid + 256 * r3;
                if (idx < 624) *(float4*)&Wtn[idx * 4] = pw[r3];
            }
        }
        __syncthreads();
    }

    float* feat = sbuf;
    #pragma unroll
    for (int n = 0; n < 7; n++) {
        if (n < ntiles) {
            int f = 8 * (nbase + n) + 2 * tq;
            float b0v = (f     < F_) ? __ldg(&conv_b[f])     : 0.f;
            float b1v = (f + 1 < F_) ? __ldg(&conv_b[f + 1]) : 0.f;
            int k0 = (f >> 3) * 8 + permk(f & 7);
            int k1 = ((f + 1) >> 3) * 8 + permk((f + 1) & 7);
            feat[(m0 + gq)     * 104 + k0] = to_tf32(fmaxf(acc[n][0] + b0v, 0.f));
            feat[(m0 + gq)     * 104 + k1] = to_tf32(fmaxf(acc[n][1] + b1v, 0.f));
            feat[(m0 + gq + 8) * 104 + k0] = to_tf32(fmaxf(acc[n][2] + b0v, 0.f));
            feat[(m0 + gq + 8) * 104 + k1] = to_tf32(fmaxf(acc[n][3] + b1v, 0.f));
        }
    }
    __syncthreads();

    const int mt  = w & 3;
    const int nb2 = (w < 4) ? 0 : 4;
    const int nt2 = (w < 4) ? 4 : 3;
    float fa[4][4];
    #pragma unroll
    for (int n = 0; n < 4; n++)
        #pragma unroll
        for (int q = 0; q < 4; q++) fa[n][q] = 0.f;

    #pragma unroll
    for (int kb = 0; kb < 13; kb++) {
        float2 aLo = *(const float2*)&feat[(mt * 16 + gq)     * 104 + kb * 8 + 2 * tq];
        float2 aHi = *(const float2*)&feat[(mt * 16 + gq + 8) * 104 + kb * 8 + 2 * tq];
        unsigned a0 = __float_as_uint(aLo.x), a2 = __float_as_uint(aLo.y);
        unsigned a1 = __float_as_uint(aHi.x), a3 = __float_as_uint(aHi.y);
        #pragma unroll
        for (int n = 0; n < 4; n++) {
            if (n < nt2) {
                float2 bb = __ldg((const float2*)&g_fcw[(8 * (nb2 + n) + gq) * 104 + kb * 8 + 2 * tq]);
                MMA_TF32_K8(fa[n], a0, a1, a2, a3,
                            __float_as_uint(bb.x), __float_as_uint(bb.y));
            }
        }
    }
    #pragma unroll
    for (int n = 0; n < 4; n++) {
        if (n < nt2) {
            int t = 8 * (nb2 + n) + 2 * tq;
            if (t < T_) {
                float bb0 = __ldg(&fc_b[t]), bb1 = __ldg(&fc_b[t + 1]);
                int s1 = s0 + mt * 16 + gq;
                *(float2*)&g_em[(b * S_ + s1)     * T_ + t] =
                    make_float2(fa[n][0] + bb0, fa[n][1] + bb1);
                *(float2*)&g_em[(b * S_ + s1 + 8) * T_ + t] =
                    make_float2(fa[n][2] + bb0, fa[n][3] + bb1);
            }
        }
    }
}

// ---------------------------------------------------------------------------
// Kernel 2: CRF, single warp per batch, linear domain.
// SHUFFLE-FREE matvec: lanes publish alpha via STS.64 into double-buffered
// pbuf; matvec reads p via 13 wide LDS (broadcast, conflict-free) on the LSU
// pipe, overlapping the 50 FMA2 on the fma pipe. One __syncwarp per step.
// ---------------------------------------------------------------------------
__global__ __launch_bounds__(32) void k_crf(
    const int* __restrict__ tags,
    const float* __restrict__ start_trans,
    const float* __restrict__ end_trans,
    const float* __restrict__ trans,
    float* __restrict__ out)
{
    __shared__ __align__(16) float pbuf[2][64];

    const int tid  = threadIdx.x;
    const int b    = blockIdx.x;
    const int base = b * S_;
    const bool act = (tid < 25);
    const int j0 = 2 * tid, j1 = 2 * tid + 1;

    // Ej0[i] = (E[2i][j0], E[2i+1][j0]); Ej1 same for j1
    uint64_t Ej0[25], Ej1[25];
    if (act) {
        #pragma unroll
        for (int i = 0; i < 25; i++) {
            float e00 = __expf(__ldg(&trans[(2 * i)     * T_ + j0]));
            float e01 = __expf(__ldg(&trans[(2 * i + 1) * T_ + j0]));
            float e10 = __expf(__ldg(&trans[(2 * i)     * T_ + j1]));
            float e11 = __expf(__ldg(&trans[(2 * i + 1) * T_ + j1]));
            PACK2(Ej0[i], e00, e01);
            PACK2(Ej1[i], e10, e11);
        }
    } else {
        #pragma unroll
        for (int i = 0; i < 25; i++) { Ej0[i] = 0ull; Ej1[i] = 0ull; }
    }

    // numerator: gold path score
    const int* tg = tags + base;
    float local = 0.f;
    for (int s = tid; s < S_; s += 32) {
        int t = __ldg(&tg[s]);
        local += __ldg(&g_em[(base + s) * T_ + t]);
        if (s < S_ - 1) local += __ldg(&trans[t * T_ + __ldg(&tg[s + 1])]);
    }
    #pragma unroll
    for (int o = 16; o; o >>= 1) local += __shfl_xor_sync(0xffffffffu, local, o);
    float s_num = local + __ldg(&start_trans[tg[0]]) + __ldg(&end_trans[tg[S_ - 1]]);

    // init alpha (log -> linear with offset)
    float al0 = -3.0e38f, al1 = -3.0e38f;
    if (act) {
        float2 e0 = *(const float2*)&g_em[base * T_ + j0];
        al0 = __ldg(&start_trans[j0]) + e0.x;
        al1 = __ldg(&start_trans[j1]) + e0.y;
    }
    float mv = fmaxf(al0, al1);
    #pragma unroll
    for (int o = 16; o; o >>= 1) mv = fmaxf(mv, __shfl_xor_sync(0xffffffffu, mv, o));
    float off = mv;
    uint64_t apk = 0ull;
    if (act) { PACK2(apk, __expf(al0 - mv), __expf(al1 - mv)); }

    // forward scan: 63 groups of 8 (s=1..504) + partial of 7
    float2 bufA[8], bufB[8];
    #pragma unroll
    for (int k = 0; k < 8; k++) { bufA[k] = make_float2(0.f, 0.f); bufB[k] = make_float2(0.f, 0.f); }
    if (act) {
        #pragma unroll
        for (int k = 0; k < 8; k++)
            bufA[k] = __ldg((const float2*)&g_em[(base + 1 + k) * T_ + j0]);
    }

    int bsel = 0;
    for (int g = 0; g < 64; g++) {
        if (g < 63 && act) {
            int sn = 8 * g + 9;
            #pragma unroll
            for (int k = 0; k < 8; k++)
                if (sn + k < S_) bufB[k] = __ldg((const float2*)&g_em[(base + sn + k) * T_ + j0]);
        }
        uint64_t eem[8];
        #pragma unroll
        for (int k = 0; k < 8; k++) {
            float e0 = __expf(bufA[k].x), e1 = __expf(bufA[k].y);
            PACK2(eem[k], e0, e1);
        }
        const int nst = (g < 63) ? 8 : 7;
        #pragma unroll
        for (int k = 0; k < 8; k++) {
            if (k >= nst) break;
            // publish alpha, then broadcast-read via wide LDS
            *(uint64_t*)&pbuf[bsel][2 * tid] = apk;
            __syncwarp();
            const ulonglong2* q2 = (const ulonglong2*)pbuf[bsel];
            uint64_t d00 = 0ull, d01 = 0ull, d10 = 0ull, d11 = 0ull;
            #pragma unroll
            for (int i = 0; i < 12; i++) {
                ulonglong2 q = q2[i];
                FMA2(d00, q.x, Ej0[2 * i]);     FMA2(d10, q.x, Ej1[2 * i]);
                FMA2(d01, q.y, Ej0[2 * i + 1]); FMA2(d11, q.y, Ej1[2 * i + 1]);
            }
            {
                uint64_t q = *(const uint64_t*)&pbuf[bsel][48];
                FMA2(d00, q, Ej0[24]); FMA2(d10, q, Ej1[24]);
            }
            float l, h;
            UNPACK2(l, h, d00); float sm0 = l + h;
            UNPACK2(l, h, d01); sm0 += l + h;
            UNPACK2(l, h, d10); float sm1 = l + h;
            UNPACK2(l, h, d11); sm1 += l + h;
            uint64_t sp;
            PACK2(sp, sm0, sm1);
            MUL2(apk, sp, eem[k]);   // inactive lanes: Ej=0 -> apk stays 0
            bsel ^= 1;
        }
        if (g < 63) {
            float a0, a1;
            UNPACK2(a0, a1, apk);
            float m = fmaxf(a0, a1);
            #pragma unroll
            for (int o = 16; o; o >>= 1) m = fmaxf(m, __shfl_xor_sync(0xffffffffu, m, o));
            float inv = 1.0f / m;
            off += __logf(m);
            uint64_t ip; PACK2(ip, inv, inv);
            MUL2(apk, apk, ip);
        }
        #pragma unroll
        for (int k = 0; k < 8; k++) bufA[k] = bufB[k];
    }

    // log_z
    float av = 0.f;
    if (act) {
        float a0, a1; UNPACK2(a0, a1, apk);
        av = a0 * __expf(__ldg(&end_trans[j0])) + a1 * __expf(__ldg(&end_trans[j1]));
    }
    #pragma unroll
    for (int o = 16; o; o >>= 1) av += __shfl_xor_sync(0xffffffffu, av, o);
    if (tid == 0) g_part[b] = (off + logf(av)) - s_num;

    // last block reduces g_part -> out, resets counter
    unsigned isl = 0;
    if (tid == 0) {
        __threadfence();
        unsigned prev = atomicAdd(&g_cnt, 1u);
        isl = (prev == B_ - 1) ? 1u : 0u;
    }
    isl = __shfl_sync(0xffffffffu, isl, 0);
    if (isl) {
        __threadfence();
        float v = g_part[tid];
        #pragma unroll
        for (int o = 16; o; o >>= 1) v += __shfl_xor_sync(0xffffffffu, v, o);
        if (tid == 0) { out[0] = v; g_cnt = 0u; }
    }
}

extern "C" void kernel_launch(void* const* d_in, const int* in_sizes, int n_in,
                              void* d_out, int out_size)
{
    const int*   x           = (const int*)  d_in[0];
    const int*   tags        = (const int*)  d_in[1];
    const float* emb         = (const float*)d_in[2];
    const float* conv_w      = (const float*)d_in[3];
    const float* conv_b      = (const float*)d_in[4];
    const float* fc_w        = (const float*)d_in[5];
    const float* fc_b        = (const float*)d_in[6];
    const float* start_trans = (const float*)d_in[7];
    const float* end_trans   = (const float*)d_in[8];
    const float* trans       = (const float*)d_in[9];
    float* out = (float*)d_out;

    // nop first: ncu's fixed capture (launch index 3) = k_crf
    k_nop<<<1, 1>>>();
    k_wt<<<(NCH * WTC + 56 * 104 + 255) / 256, 256>>>(conv_w, fc_w);
    k_emissions<<<dim3(S_ / 64, B_), 256>>>(x, emb, conv_b, fc_b);
    k_crf<<<B_, 32>>>(tags, start_trans, end_trans, trans, out);
}